// round 16
// baseline (speedup 1.0000x reference)
#include <cuda_runtime.h>
#include <math.h>

#define VOCAB   32000
#define NB      8
#define NS      512
#define NROWS   (NB * NS)          // 4096
#define HALF4   4000               // float4 per half-row
#define EPS_LS  0.1f
#define REP_W   0.2f
#define IGN     (-100)

// Scratch (device globals — zero-initialized at load; k_fin resets g_done
// after every execution so graph replays stay deterministic)
__device__ int      g_argmax[NROWS];   // per-row argmax (-1 if invalid)
__device__ float    g_pertok[NROWS];
__device__ float    g_validf[NROWS];
__device__ float    g_psl[NB];         // per-batch sum ln(c_i) = sum c*ln c
__device__ int      g_pnu[NB];         // per-batch # unique bins
__device__ float    g_ppp[NB];         // per-batch CE numerator partial
__device__ float    g_ppv[NB];         // per-batch valid count
__device__ unsigned g_done;

// ---------------------------------------------------------------------------
// kernel 1: 1024 blocks x 256 thr. 4 rows/block, 2 warps per half-row.
// Single balanced wave, ~6.4 TB/s — at the practical HBM ceiling. FROZEN
// (identical to the R10 kernel that measured 82 us / 6.4 TB/s).
// ---------------------------------------------------------------------------
#define PROC(v, f4i)                                                        \
    do {                                                                    \
        int gb = half * (HALF4 * 4) + 4 * (f4i);                            \
        s0 += __expf((v).x); s1 += __expf((v).y);                           \
        s0 += __expf((v).z); s1 += __expf((v).w);                           \
        sx0 += (v).x; sx1 += (v).y; sx0 += (v).z; sx1 += (v).w;             \
        if ((v).x > m) { m = (v).x; ai = gb;     }                          \
        if ((v).y > m) { m = (v).y; ai = gb + 1; }                          \
        if ((v).z > m) { m = (v).z; ai = gb + 2; }                          \
        if ((v).w > m) { m = (v).w; ai = gb + 3; }                          \
    } while (0)

__global__ __launch_bounds__(256, 7)
void k_row(const float* __restrict__ logits, const void* __restrict__ labels)
{
    const int tid  = threadIdx.x;
    const int warp = tid >> 5;
    const int lane = tid & 31;

    // label dtype detection (int64 LE hi-words are 0/-1; first 4096 int32
    // words are in-bounds under both dtypes) — R10-proven variant
    int bad = 0;
    for (int j = 1 + 2 * tid; j < NROWS; j += 2 * 256) {
        int v = ((const int*)labels)[j];
        bad |= (v != 0 && v != -1);
    }
    const int lab64 = !__syncthreads_or(bad);

    const int row  = blockIdx.x * 4 + (warp >> 1);
    const int half = warp & 1;
    const float4* p = (const float4*)(logits + (size_t)row * VOCAB) +
                      half * HALF4 + lane;

    float m = -INFINITY; int ai = 0x7FFFFFFF;
    float s0 = 0.f, s1 = 0.f, sx0 = 0.f, sx1 = 0.f;

    #pragma unroll 1
    for (int it = 0; it < 31; ++it) {
        const float4* q = p + it * 128;
        float4 v0 = __ldcs(q);
        float4 v1 = __ldcs(q + 32);
        float4 v2 = __ldcs(q + 64);
        float4 v3 = __ldcs(q + 96);
        int f4 = lane + it * 128;
        PROC(v0, f4);
        PROC(v1, f4 + 32);
        PROC(v2, f4 + 64);
        PROC(v3, f4 + 96);
    }
    {
        float4 v = __ldcs(p + 3968);
        PROC(v, lane + 3968);
    }

    float s = s0 + s1, sx = sx0 + sx1;
    #pragma unroll
    for (int o = 16; o > 0; o >>= 1) {
        float m2  = __shfl_xor_sync(0xFFFFFFFFu, m,  o);
        int   i2  = __shfl_xor_sync(0xFFFFFFFFu, ai, o);
        float s2  = __shfl_xor_sync(0xFFFFFFFFu, s,  o);
        float sx2 = __shfl_xor_sync(0xFFFFFFFFu, sx, o);
        s += s2; sx += sx2;
        if (m2 > m || (m2 == m && i2 < ai)) { m = m2; ai = i2; }
    }

    __shared__ float sh_s[8], sh_sx[8], sh_m[8];
    __shared__ int   sh_i[8];
    if (lane == 0) { sh_s[warp] = s; sh_sx[warp] = sx; sh_m[warp] = m; sh_i[warp] = ai; }
    __syncthreads();

    if (tid < 4) {
        int w0 = 2 * tid, w1 = w0 + 1;
        float S  = sh_s[w0] + sh_s[w1];
        float SX = sh_sx[w0] + sh_sx[w1];
        float M  = sh_m[w0]; int AI = sh_i[w0];
        if (sh_m[w1] > M || (sh_m[w1] == M && sh_i[w1] < AI)) { M = sh_m[w1]; AI = sh_i[w1]; }

        int r = blockIdx.x * 4 + tid;
        long long lbl;
        if (lab64) lbl = ((const long long*)labels)[r];
        else       lbl = (long long)(((const int*)labels)[r]);
        bool valid = (lbl != IGN);
        int  safe  = valid ? (int)lbl : 0;
        float xl   = __ldg(logits + (size_t)r * VOCAB + safe);
        float per  = logf(S) - (1.f - EPS_LS) * xl - EPS_LS * (SX / (float)VOCAB);
        g_pertok[r] = valid ? per : 0.f;
        g_validf[r] = valid ? 1.f : 0.f;
        g_argmax[r] = valid ? AI : -1;
    }
}

// ---------------------------------------------------------------------------
// kernel 2: 8 blocks, one per batch. No histogram: all-pairs multiplicity.
//   sum_bins c*ln c = sum_i ln(c_i)          (c_i = multiplicity of v_i)
//   n_unique       = sum_i [first occurrence]
// 512 values in smem; each thread handles 2 positions, sweeps all 512
// (smem broadcast). Fully deterministic. CE partials inline. Last-done
// block combines the 8 per-batch partials in fixed order.
// ---------------------------------------------------------------------------
__global__ __launch_bounds__(256)
void k_fin(float* __restrict__ out, int out_size)
{
    __shared__ int   vals[NS];
    __shared__ float s_sl[256], s_pp[256], s_pv[256];
    __shared__ int   s_nu[256];
    __shared__ int   sh_last;

    const int tid = threadIdx.x;
    const int b   = blockIdx.x;
    const int r0  = b * NS;

    int v0 = g_argmax[r0 + tid];
    int v1 = g_argmax[r0 + 256 + tid];
    float pp = g_pertok[r0 + tid] + g_pertok[r0 + 256 + tid];
    float pv = g_validf[r0 + tid] + g_validf[r0 + 256 + tid];
    vals[tid]       = v0;
    vals[tid + 256] = v1;
    __syncthreads();

    const int i0 = tid, i1 = tid + 256;
    int c0 = 0, c1 = 0, cb0 = 0, cb1 = 0;
    #pragma unroll 8
    for (int j = 0; j < NS; ++j) {
        int w  = vals[j];
        int e0 = (w == v0);
        int e1 = (w == v1);
        c0 += e0;  c1 += e1;
        cb0 += e0 & (j < i0);
        cb1 += e1 & (j < i1);
    }
    float sl = 0.f; int nu = 0;
    if (v0 >= 0) { sl += logf((float)c0); nu += (cb0 == 0); }
    if (v1 >= 0) { sl += logf((float)c1); nu += (cb1 == 0); }

    s_sl[tid] = sl; s_pp[tid] = pp; s_pv[tid] = pv; s_nu[tid] = nu;
    __syncthreads();
    for (int o = 128; o > 0; o >>= 1) {
        if (tid < o) {
            s_sl[tid] += s_sl[tid + o];
            s_pp[tid] += s_pp[tid + o];
            s_pv[tid] += s_pv[tid + o];
            s_nu[tid] += s_nu[tid + o];
        }
        __syncthreads();
    }

    if (tid == 0) {
        g_psl[b] = s_sl[0];
        g_pnu[b] = s_nu[0];
        g_ppp[b] = s_pp[0];
        g_ppv[b] = s_pv[0];
        __threadfence();
        unsigned prev = atomicAdd(&g_done, 1u);
        sh_last = (prev == NB - 1);
    }
    __syncthreads();
    if (!sh_last) return;

    __shared__ float sh_rep[NB];
    if (tid < NB) {
        float T  = g_ppv[tid];          // histogram mass == valid count
        float SL = g_psl[tid];
        int   NU = g_pnu[tid];
        float rep = 0.f;
        if (T > 0.f) {
            float ent = logf(T) - SL / T;
            rep = 1.f - ent / logf((float)NU + 1.f);
        }
        sh_rep[tid] = rep;
    }
    __syncthreads();

    if (tid == 0) {
        float P = 0.f, Vv = 0.f, R = 0.f;
        #pragma unroll
        for (int k = 0; k < NB; ++k) {
            P  += g_ppp[k];
            Vv += g_ppv[k];
            R  += sh_rep[k];
        }
        float ce  = P / fmaxf(Vv, 1.f);
        float rep = R / (float)NB;
        out[0] = ce + REP_W * rep;
        if (out_size > 1) out[1] = ce;
        if (out_size > 2) out[2] = rep;
        atomicExch(&g_done, 0u);   // hardened reset for next graph replay
    }
}

extern "C" void kernel_launch(void* const* d_in, const int* in_sizes, int n_in,
                              void* d_out, int out_size)
{
    const float* logits = (const float*)d_in[0];
    const void*  labels = d_in[1];
    (void)n_in; (void)in_sizes;

    k_row<<<NROWS / 4, 256>>>(logits, labels);
    k_fin<<<NB, 256>>>((float*)d_out, out_size);
}